// round 12
// baseline (speedup 1.0000x reference)
#include <cuda_runtime.h>

#define N_NODES 120000
#define N_EDGES 1000000
#define DIM 64
#define N_LAYERS 3
#define OUT_STRIDE 256   // (N_LAYERS+1)*DIM
#define NB 8             // nodes per warp
#define SCAN_TB 1024
#define SCAN_BLOCKS ((N_NODES + SCAN_TB - 1) / SCAN_TB)  // 118

typedef unsigned long long u64;

// ---------------- scratch ----------------
__device__ int   g_degcol[N_NODES];
__device__ int   g_degrow[N_NODES];
__device__ float g_dinv[N_NODES];
__device__ int   g_rowptr[N_NODES + 1];
__device__ int   g_cursor[N_NODES];
__device__ int   g_blocksum[SCAN_BLOCKS];
__device__ int2  g_edges[N_EDGES];   // CSR-ordered {col, __float_as_int(norm)}

// ---------------- packed f32x2 helpers ----------------
__device__ __forceinline__ u64 fma2(u64 a, u64 b, u64 c) {
    u64 d;
    asm("fma.rn.f32x2 %0, %1, %2, %3;" : "=l"(d) : "l"(a), "l"(b), "l"(c));
    return d;
}
__device__ __forceinline__ u64 pack2(float lo, float hi) {
    u64 d;
    asm("mov.b64 %0, {%1, %2};" : "=l"(d) : "f"(lo), "f"(hi));
    return d;
}
__device__ __forceinline__ u64 dup2(float v) {
    u64 d;
    asm("mov.b64 %0, {%1, %1};" : "=l"(d) : "f"(v));
    return d;
}
__device__ __forceinline__ float2 unpack2(u64 v) {
    float lo, hi;
    asm("mov.b64 {%0, %1}, %2;" : "=f"(lo), "=f"(hi) : "l"(v));
    return make_float2(lo, hi);
}

// ---------------- setup ----------------
__global__ void init_kernel() {
    int i = blockIdx.x * blockDim.x + threadIdx.x;
    if (i < N_NODES) { g_degcol[i] = 0; g_degrow[i] = 0; }
}

__global__ void hist_kernel(const int* __restrict__ ei) {
    int e = blockIdx.x * blockDim.x + threadIdx.x;
    if (e >= N_EDGES) return;
    atomicAdd(&g_degrow[ei[e]], 1);
    atomicAdd(&g_degcol[ei[N_EDGES + e]], 1);
}

// scan_a also finalizes dinv (same N-domain; dinv only read by scatter, later)
__global__ void scan_a_kernel() {
    __shared__ int wsum[32];
    int tid = threadIdx.x, lane = tid & 31, wid = tid >> 5;
    int i = blockIdx.x * SCAN_TB + tid;
    if (i < N_NODES) {
        int d = g_degcol[i];
        g_dinv[i] = (d > 0) ? rsqrtf((float)d) : 0.f;
    }
    int v = (i < N_NODES) ? g_degrow[i] : 0;
    int x = v;
#pragma unroll
    for (int off = 1; off < 32; off <<= 1) {
        int y = __shfl_up_sync(0xffffffffu, x, off);
        if (lane >= off) x += y;
    }
    if (lane == 31) wsum[wid] = x;
    __syncthreads();
    if (wid == 0) {
        int w = wsum[lane];
#pragma unroll
        for (int off = 1; off < 32; off <<= 1) {
            int y = __shfl_up_sync(0xffffffffu, w, off);
            if (lane >= off) w += y;
        }
        wsum[lane] = w;
    }
    __syncthreads();
    int excl = ((wid > 0) ? wsum[wid - 1] : 0) + x - v;
    if (i < N_NODES) g_rowptr[i] = excl;
    if (tid == SCAN_TB - 1) g_blocksum[blockIdx.x] = excl + v;
}

__global__ void scan_b_kernel() {
    __shared__ int ws[4];
    int tid = threadIdx.x, lane = tid & 31, wid = tid >> 5;
    int v = (tid < SCAN_BLOCKS) ? g_blocksum[tid] : 0;
    int x = v;
#pragma unroll
    for (int off = 1; off < 32; off <<= 1) {
        int y = __shfl_up_sync(0xffffffffu, x, off);
        if (lane >= off) x += y;
    }
    if (lane == 31) ws[wid] = x;
    __syncthreads();
    int carry = 0;
    for (int k = 0; k < wid; k++) carry += ws[k];
    if (tid < SCAN_BLOCKS) g_blocksum[tid] = carry + x - v;
}

__global__ void scan_c_kernel() {
    int i = blockIdx.x * SCAN_TB + threadIdx.x;
    if (i < N_NODES) {
        int r = g_rowptr[i] + g_blocksum[blockIdx.x];
        g_rowptr[i] = r;
        g_cursor[i] = r;
    }
    if (i == 0) g_rowptr[N_NODES] = N_EDGES;
}

__global__ void scatter_kernel(const int* __restrict__ ei) {
    int e = blockIdx.x * blockDim.x + threadIdx.x;
    if (e >= N_EDGES) return;
    int r = ei[e];
    int c = ei[N_EDGES + e];
    float nv = g_dinv[r] * g_dinv[c];
    int pos = atomicAdd(&g_cursor[r], 1);
    g_edges[pos] = make_int2(c, __float_as_int(nv));
}

__global__ void copy_emb_kernel(const float* __restrict__ emb, float* __restrict__ out) {
    int i = blockIdx.x * blockDim.x + threadIdx.x;
    if (i >= N_NODES * (DIM / 4)) return;
    int r = i >> 4;
    int q = i & 15;
    ((float4*)out)[(size_t)r * (OUT_STRIDE / 4) + q] = ((const float4*)emb)[i];
}

// ---------------- fused layer ----------------
// 256 threads (8 warps); each warp owns NB=8 nodes.
// GATHER: two half-warps process different edges in parallel (16 lanes x float4 dims),
//         with x2 manual step -> 4 independent rec->x chains in flight per warp.
// GEMV:   lane owns dims {2*lane, 2*lane+1}; interleaved weights, one LDS.128 per k;
//         accumulators staged in smem as (a1,a2) pairs; fma.rn.f32x2 math.
__global__ __launch_bounds__(256) void fused_layer_kernel(
    const float* __restrict__ W1, const float* __restrict__ b1,
    const float* __restrict__ W2, const float* __restrict__ b2,
    float* __restrict__ out, int loff) {
    extern __shared__ char smem[];
    float* sW = (float*)smem;              // [k*32+l] float4 = (W1[2l][k],W1[2l+1][k],W2[2l][k],W2[2l+1][k])
    float* sb = sW + 2 * DIM * DIM;        // 64 floats
    float2* sacc = (float2*)(sb + DIM);    // [8 warps][NB][64] float2 (a1[k], a2[k])

    int tid = threadIdx.x;
    for (int i = tid; i < DIM * DIM; i += 256) {
        int d = i >> 6, k = i & 63;
        int slot = (k * 32 + (d >> 1)) * 4 + (d & 1);
        sW[slot] = W1[i];
        sW[slot + 2] = W2[i];
    }
    if (tid < DIM) sb[tid] = b1[tid] + b2[tid];
    __syncthreads();

    int lane = tid & 31;
    int g = lane >> 4;       // half-warp id (edge parity)
    int q = lane & 15;       // dim quarter: dims 4q..4q+3
    int w = tid >> 5;
    int base = (blockIdx.x * 8 + w) * NB;  // grid exact: 1875*64 = 120000
    const float* x = out + loff;
    float2* macc = sacc + (size_t)w * (NB * DIM);

    float sv[NB];
#pragma unroll
    for (int j = 0; j < NB; j++) {
        int n = base + j;
        int s0 = g_rowptr[n], s1 = g_rowptr[n + 1];
        float4 a = make_float4(0.f, 0.f, 0.f, 0.f);
        float s = 0.f;
        int e = s0 + g;
        // half-warp strides by 2; unroll x2 -> 2 chains per half, 4 per warp
        for (; e + 2 < s1; e += 4) {
            int2 rA = g_edges[e];
            int2 rB = g_edges[e + 2];
            const float4 xA = *(const float4*)(x + (size_t)rA.x * OUT_STRIDE + 4 * q);
            const float4 xB = *(const float4*)(x + (size_t)rB.x * OUT_STRIDE + 4 * q);
            float nA = __int_as_float(rA.y), nB = __int_as_float(rB.y);
            a.x += nA * xA.x + nB * xB.x;
            a.y += nA * xA.y + nB * xB.y;
            a.z += nA * xA.z + nB * xB.z;
            a.w += nA * xA.w + nB * xB.w;
            s += nA + nB;
        }
        if (e < s1) {
            int2 rc = g_edges[e];
            float nv = __int_as_float(rc.y);
            const float4 xc = *(const float4*)(x + (size_t)rc.x * OUT_STRIDE + 4 * q);
            a.x += nv * xc.x;
            a.y += nv * xc.y;
            a.z += nv * xc.z;
            a.w += nv * xc.w;
            s += nv;
        }
        // combine the two half-warps (lane L <-> L^16 hold same dims)
        a.x += __shfl_xor_sync(0xffffffffu, a.x, 16);
        a.y += __shfl_xor_sync(0xffffffffu, a.y, 16);
        a.z += __shfl_xor_sync(0xffffffffu, a.z, 16);
        a.w += __shfl_xor_sync(0xffffffffu, a.w, 16);
        s += __shfl_xor_sync(0xffffffffu, s, 16);
        sv[j] = s;
        if (g == 0) {
            const float4 xr = *(const float4*)(x + (size_t)n * OUT_STRIDE + 4 * q);
            float2* mp = &macc[j * DIM + 4 * q];
            *(float4*)&mp[0] = make_float4(a.x, a.x * xr.x, a.y, a.y * xr.y);
            *(float4*)&mp[2] = make_float4(a.z, a.z * xr.z, a.w, a.w * xr.w);
        }
    }
    __syncwarp();

    const ulonglong2* sWp = (const ulonglong2*)sW;  // [k*32+lane] = {w1 pair, w2 pair}
    float2 bf = unpack2(((const u64*)sb)[lane]);
    u64 y[NB];
#pragma unroll
    for (int j = 0; j < NB; j++) y[j] = pack2(sv[j] * bf.x, sv[j] * bf.y);

#pragma unroll 8
    for (int k = 0; k < DIM; k++) {
        ulonglong2 wq = sWp[k * 32 + lane];   // one LDS.128: w1 pair + w2 pair
#pragma unroll
        for (int j = 0; j < NB; j++) {
            float2 aa = macc[j * DIM + k];    // broadcast LDS.64
            y[j] = fma2(dup2(aa.x), wq.x, y[j]);
            y[j] = fma2(dup2(aa.y), wq.y, y[j]);
        }
    }

#pragma unroll
    for (int j = 0; j < NB; j++) {
        int n = base + j;
        float2 v = unpack2(y[j]);
        v.x = v.x >= 0.f ? v.x : 0.2f * v.x;
        v.y = v.y >= 0.f ? v.y : 0.2f * v.y;
        *(float2*)(out + (size_t)n * OUT_STRIDE + loff + DIM + 2 * lane) = v;
    }
}

// ---------------- launch ----------------
extern "C" void kernel_launch(void* const* d_in, const int* in_sizes, int n_in,
                              void* d_out, int out_size) {
    const int* edge_index = (const int*)d_in[0];   // [2,E] int32
    const float* emb = (const float*)d_in[1];
    const float* W1 = (const float*)d_in[2];
    const float* b1 = (const float*)d_in[3];
    const float* W2 = (const float*)d_in[4];
    const float* b2 = (const float*)d_in[5];
    float* out = (float*)d_out;

    const int TB = 256;
    const int NBLK = (N_NODES + TB - 1) / TB;
    const int EBLK = (N_EDGES + TB - 1) / TB;

    init_kernel<<<NBLK, TB>>>();
    hist_kernel<<<EBLK, TB>>>(edge_index);
    scan_a_kernel<<<SCAN_BLOCKS, SCAN_TB>>>();   // includes dinv finalize
    scan_b_kernel<<<1, 128>>>();
    scan_c_kernel<<<SCAN_BLOCKS, SCAN_TB>>>();
    scatter_kernel<<<EBLK, TB>>>(edge_index);

    copy_emb_kernel<<<(N_NODES * (DIM / 4) + TB - 1) / TB, TB>>>(emb, out);

    // dynamic smem: weights 32.25 KB + acc staging 32 KB = 64.25 KB -> 3 blocks/SM
    const int SMEM_BYTES = (2 * DIM * DIM + DIM) * 4 + 8 * NB * DIM * 8;  // 65792
    cudaFuncSetAttribute(fused_layer_kernel, cudaFuncAttributeMaxDynamicSharedMemorySize, SMEM_BYTES);

    const int FBLK = N_NODES / 64;  // 1875 exact
    for (int l = 0; l < N_LAYERS; l++) {
        fused_layer_kernel<<<FBLK, 256, SMEM_BYTES>>>(
            W1 + l * DIM * DIM, b1 + l * DIM,
            W2 + l * DIM * DIM, b2 + l * DIM,
            out, l * DIM);
    }
}

// round 13
// speedup vs baseline: 1.2290x; 1.2290x over previous
#include <cuda_runtime.h>

#define N_NODES 120000
#define N_EDGES 1000000
#define DIM 64
#define N_LAYERS 3
#define OUT_STRIDE 256   // (N_LAYERS+1)*DIM
#define NB 8             // nodes per warp
#define SCAN_TB 1024
#define SCAN_BLOCKS ((N_NODES + SCAN_TB - 1) / SCAN_TB)  // 118

typedef unsigned long long u64;

// ---------------- scratch ----------------
__device__ int   g_degcol[N_NODES];
__device__ int   g_degrow[N_NODES];
__device__ float g_dinv[N_NODES];
__device__ int   g_rowptr[N_NODES + 1];
__device__ int   g_cursor[N_NODES];
__device__ int   g_blocksum[SCAN_BLOCKS];
__device__ int2  g_edges[N_EDGES];   // CSR-ordered {col*OUT_STRIDE, __float_as_int(norm)}

// ---------------- packed f32x2 helpers ----------------
__device__ __forceinline__ u64 fma2(u64 a, u64 b, u64 c) {
    u64 d;
    asm("fma.rn.f32x2 %0, %1, %2, %3;" : "=l"(d) : "l"(a), "l"(b), "l"(c));
    return d;
}
__device__ __forceinline__ u64 pack2(float lo, float hi) {
    u64 d;
    asm("mov.b64 %0, {%1, %2};" : "=l"(d) : "f"(lo), "f"(hi));
    return d;
}
__device__ __forceinline__ float2 unpack2(u64 v) {
    float lo, hi;
    asm("mov.b64 {%0, %1}, %2;" : "=f"(lo), "=f"(hi) : "l"(v));
    return make_float2(lo, hi);
}

// ---------------- setup ----------------
__global__ void init_kernel() {
    int i = blockIdx.x * blockDim.x + threadIdx.x;
    if (i < N_NODES) { g_degcol[i] = 0; g_degrow[i] = 0; }
}

__global__ void hist_kernel(const int* __restrict__ ei) {
    int e = blockIdx.x * blockDim.x + threadIdx.x;
    if (e >= N_EDGES) return;
    atomicAdd(&g_degrow[ei[e]], 1);
    atomicAdd(&g_degcol[ei[N_EDGES + e]], 1);
}

// scan_a also finalizes dinv (same N-domain; dinv only read by scatter, later)
__global__ void scan_a_kernel() {
    __shared__ int wsum[32];
    int tid = threadIdx.x, lane = tid & 31, wid = tid >> 5;
    int i = blockIdx.x * SCAN_TB + tid;
    if (i < N_NODES) {
        int d = g_degcol[i];
        g_dinv[i] = (d > 0) ? rsqrtf((float)d) : 0.f;
    }
    int v = (i < N_NODES) ? g_degrow[i] : 0;
    int x = v;
#pragma unroll
    for (int off = 1; off < 32; off <<= 1) {
        int y = __shfl_up_sync(0xffffffffu, x, off);
        if (lane >= off) x += y;
    }
    if (lane == 31) wsum[wid] = x;
    __syncthreads();
    if (wid == 0) {
        int w = wsum[lane];
#pragma unroll
        for (int off = 1; off < 32; off <<= 1) {
            int y = __shfl_up_sync(0xffffffffu, w, off);
            if (lane >= off) w += y;
        }
        wsum[lane] = w;
    }
    __syncthreads();
    int excl = ((wid > 0) ? wsum[wid - 1] : 0) + x - v;
    if (i < N_NODES) g_rowptr[i] = excl;
    if (tid == SCAN_TB - 1) g_blocksum[blockIdx.x] = excl + v;
}

__global__ void scan_b_kernel() {
    __shared__ int ws[4];
    int tid = threadIdx.x, lane = tid & 31, wid = tid >> 5;
    int v = (tid < SCAN_BLOCKS) ? g_blocksum[tid] : 0;
    int x = v;
#pragma unroll
    for (int off = 1; off < 32; off <<= 1) {
        int y = __shfl_up_sync(0xffffffffu, x, off);
        if (lane >= off) x += y;
    }
    if (lane == 31) ws[wid] = x;
    __syncthreads();
    int carry = 0;
    for (int k = 0; k < wid; k++) carry += ws[k];
    if (tid < SCAN_BLOCKS) g_blocksum[tid] = carry + x - v;
}

__global__ void scan_c_kernel() {
    int i = blockIdx.x * SCAN_TB + threadIdx.x;
    if (i < N_NODES) {
        int r = g_rowptr[i] + g_blocksum[blockIdx.x];
        g_rowptr[i] = r;
        g_cursor[i] = r;
    }
    if (i == 0) g_rowptr[N_NODES] = N_EDGES;
}

__global__ void scatter_kernel(const int* __restrict__ ei) {
    int e = blockIdx.x * blockDim.x + threadIdx.x;
    if (e >= N_EDGES) return;
    int r = ei[e];
    int c = ei[N_EDGES + e];
    float nv = g_dinv[r] * g_dinv[c];
    int pos = atomicAdd(&g_cursor[r], 1);
    g_edges[pos] = make_int2(c * OUT_STRIDE, __float_as_int(nv));  // pre-scaled column
}

__global__ void copy_emb_kernel(const float* __restrict__ emb, float* __restrict__ out) {
    int i = blockIdx.x * blockDim.x + threadIdx.x;
    if (i >= N_NODES * (DIM / 4)) return;
    int r = i >> 4;
    int q = i & 15;
    ((float4*)out)[(size_t)r * (OUT_STRIDE / 4) + q] = ((const float4*)emb)[i];
}

// ---------------- fused layer: CSR gather + k-pair FFMA2 GEMV (no dup MOVs) ----------------
// 256 threads (8 warps); warp owns NB=8 nodes; lane owns output dims {2l, 2l+1}.
// acc staged per (node, k-group g) as float4 (a1[2g], a1[2g+1], a2[2g], a2[2g+1]);
// GEMV accumulates k-pair partials: p[d] += (a1 pair)*(W1[d] k-pair) + (a2 pair)*(W2[d] k-pair),
// final y[d] = p.x + p.y. Every FFMA2 operand loads as a natural adjacent pair.
__global__ __launch_bounds__(256, 3) void fused_layer_kernel(
    const float* __restrict__ W1, const float* __restrict__ b1,
    const float* __restrict__ W2, const float* __restrict__ b2,
    float* __restrict__ out, int loff) {
    extern __shared__ char smem[];
    ulonglong2* sW1q = (ulonglong2*)smem;        // [g*32+l] = {W1[2l] k-pair, W1[2l+1] k-pair} 16KB
    ulonglong2* sW2q = sW1q + 32 * 32;           // 16KB
    float* sb = (float*)(sW2q + 32 * 32);        // 64 floats
    ulonglong2* sacc = (ulonglong2*)(sb + 64);   // [8 warps][NB][32 g] = 32KB

    int tid = threadIdx.x;
    {
        const float2* W1f = (const float2*)W1;   // [d][32] k-pairs
        const float2* W2f = (const float2*)W2;
        for (int i = tid; i < 1024; i += 256) {
            int g = i >> 5, l = i & 31;
            float2 w1a = W1f[(2 * l) * 32 + g];
            float2 w1b = W1f[(2 * l + 1) * 32 + g];
            float2 w2a = W2f[(2 * l) * 32 + g];
            float2 w2b = W2f[(2 * l + 1) * 32 + g];
            *(float4*)&sW1q[i] = make_float4(w1a.x, w1a.y, w1b.x, w1b.y);
            *(float4*)&sW2q[i] = make_float4(w2a.x, w2a.y, w2b.x, w2b.y);
        }
    }
    if (tid < DIM) sb[tid] = b1[tid] + b2[tid];
    __syncthreads();

    int lane = tid & 31;
    int w = tid >> 5;
    int base = (blockIdx.x * 8 + w) * NB;   // grid exact: 1875*64 = 120000
    const float* x = out + loff;
    ulonglong2* macc = sacc + (size_t)w * (NB * 32);

    float sv[NB];
#pragma unroll
    for (int j = 0; j < NB; j++) {
        float ax = 0.f, ay = 0.f, s = 0.f;
        int n = base + j;
        int s0 = g_rowptr[n], s1 = g_rowptr[n + 1];
        float2 xr = *(const float2*)(x + (size_t)n * OUT_STRIDE + 2 * lane);
        int e = s0;
        for (; e + 2 <= s1; e += 2) {   // two independent rec->x chains
            int2 rA = g_edges[e];
            int2 rB = g_edges[e + 1];
            float2 xA = *(const float2*)(x + rA.x + 2 * lane);
            float2 xB = *(const float2*)(x + rB.x + 2 * lane);
            float nA = __int_as_float(rA.y), nB = __int_as_float(rB.y);
            ax += nA * xA.x + nB * xB.x;
            ay += nA * xA.y + nB * xB.y;
            s += nA + nB;
        }
        if (e < s1) {
            int2 rc = g_edges[e];
            float nv = __int_as_float(rc.y);
            float2 xc = *(const float2*)(x + rc.x + 2 * lane);
            ax += nv * xc.x;
            ay += nv * xc.y;
            s += nv;
        }
        sv[j] = s;
        // lane l owns k-group g=l: (a1[2l], a1[2l+1], a2[2l], a2[2l+1]) — one STS.128
        *(float4*)&macc[j * 32 + lane] = make_float4(ax, ay, ax * xr.x, ay * xr.y);
    }
    __syncwarp();

    float2 bf = *(const float2*)&sb[2 * lane];
    u64 p0[NB], p1[NB];
#pragma unroll
    for (int j = 0; j < NB; j++) {
        p0[j] = pack2(sv[j] * bf.x, 0.f);
        p1[j] = pack2(sv[j] * bf.y, 0.f);
    }

#pragma unroll 4
    for (int g = 0; g < 32; g++) {
        ulonglong2 w1 = sW1q[g * 32 + lane];   // LDS.128, conflict-free
        ulonglong2 w2 = sW2q[g * 32 + lane];
#pragma unroll
        for (int j = 0; j < NB; j++) {
            ulonglong2 aa = macc[j * 32 + g];  // LDS.128 broadcast: {a1 pair, a2 pair}
            p0[j] = fma2(aa.x, w1.x, p0[j]);
            p0[j] = fma2(aa.y, w2.x, p0[j]);
            p1[j] = fma2(aa.x, w1.y, p1[j]);
            p1[j] = fma2(aa.y, w2.y, p1[j]);
        }
    }

#pragma unroll
    for (int j = 0; j < NB; j++) {
        int n = base + j;
        float2 q0 = unpack2(p0[j]);
        float2 q1 = unpack2(p1[j]);
        float vx = q0.x + q0.y;
        float vy = q1.x + q1.y;
        vx = vx >= 0.f ? vx : 0.2f * vx;
        vy = vy >= 0.f ? vy : 0.2f * vy;
        *(float2*)(out + (size_t)n * OUT_STRIDE + loff + DIM + 2 * lane) = make_float2(vx, vy);
    }
}

// ---------------- launch ----------------
extern "C" void kernel_launch(void* const* d_in, const int* in_sizes, int n_in,
                              void* d_out, int out_size) {
    const int* edge_index = (const int*)d_in[0];   // [2,E] int32
    const float* emb = (const float*)d_in[1];
    const float* W1 = (const float*)d_in[2];
    const float* b1 = (const float*)d_in[3];
    const float* W2 = (const float*)d_in[4];
    const float* b2 = (const float*)d_in[5];
    float* out = (float*)d_out;

    const int TB = 256;
    const int NBLK = (N_NODES + TB - 1) / TB;
    const int EBLK = (N_EDGES + TB - 1) / TB;

    init_kernel<<<NBLK, TB>>>();
    hist_kernel<<<EBLK, TB>>>(edge_index);
    scan_a_kernel<<<SCAN_BLOCKS, SCAN_TB>>>();   // includes dinv finalize
    scan_b_kernel<<<1, 128>>>();
    scan_c_kernel<<<SCAN_BLOCKS, SCAN_TB>>>();
    scatter_kernel<<<EBLK, TB>>>(edge_index);

    copy_emb_kernel<<<(N_NODES * (DIM / 4) + TB - 1) / TB, TB>>>(emb, out);

    // dynamic smem: weights 32 KB + bias 256B + acc staging 32 KB = 64.25 KB -> 3 blocks/SM
    const int SMEM_BYTES = 32 * 32 * 16 * 2 + 256 + 8 * NB * 32 * 16;  // 65792
    cudaFuncSetAttribute(fused_layer_kernel, cudaFuncAttributeMaxDynamicSharedMemorySize, SMEM_BYTES);

    const int FBLK = N_NODES / 64;  // 1875 exact
    for (int l = 0; l < N_LAYERS; l++) {
        fused_layer_kernel<<<FBLK, 256, SMEM_BYTES>>>(
            W1 + l * DIM * DIM, b1 + l * DIM,
            W2 + l * DIM * DIM, b2 + l * DIM,
            out, l * DIM);
    }
}